// round 1
// baseline (speedup 1.0000x reference)
#include <cuda_runtime.h>
#include <cstdint>
#include <math.h>

// Problem dims
#define B_   64
#define S_   512
#define H_   1024
#define IN_  1024
#define G4   4096   // 4*H

// ---------------- device scratch (no runtime allocation allowed) ----------------
__device__ float g_Wi[(size_t)G4 * IN_];          // 16 MB  packed [i;f;g;o] x IN
__device__ float g_Wh[(size_t)G4 * H_];           // 16 MB  packed [i;f;g;o] x H
__device__ float g_bias[G4];                      // b_i* + b_h*
__device__ float g_xp[(size_t)S_ * B_ * G4];      // 512 MB  x_proj, layout [t][b][4H]
__device__ float g_h[2][B_ * H_];                 // double-buffered hidden state
__device__ float g_c[B_ * H_];                    // cell state

// ---------------- helpers ----------------
__device__ __forceinline__ unsigned f2tf(float x) {
    unsigned u;
    asm("cvt.rna.tf32.f32 %0, %1;" : "=r"(u) : "f"(x));
    return u;
}

__device__ __forceinline__ void mma8(float* d, const unsigned* a, const unsigned* b) {
    asm volatile(
        "mma.sync.aligned.m16n8k8.row.col.f32.tf32.tf32.f32 "
        "{%0,%1,%2,%3}, {%4,%5,%6,%7}, {%8,%9}, {%0,%1,%2,%3};\n"
        : "+f"(d[0]), "+f"(d[1]), "+f"(d[2]), "+f"(d[3])
        : "r"(a[0]), "r"(a[1]), "r"(a[2]), "r"(a[3]), "r"(b[0]), "r"(b[1]));
}

// ---------------- setup kernels ----------------
__global__ void pack_wi(const float* __restrict__ src, int gate) {
    int i = blockIdx.x * blockDim.x + threadIdx.x;     // over float4s
    const int n4 = H_ * IN_ / 4;
    if (i < n4)
        reinterpret_cast<float4*>(g_Wi)[(size_t)gate * n4 + i] =
            reinterpret_cast<const float4*>(src)[i];
}

__global__ void pack_wh(const float* __restrict__ src, int gate) {
    int i = blockIdx.x * blockDim.x + threadIdx.x;
    const int n4 = H_ * H_ / 4;
    if (i < n4)
        reinterpret_cast<float4*>(g_Wh)[(size_t)gate * n4 + i] =
            reinterpret_cast<const float4*>(src)[i];
}

__global__ void build_bias(const float* __restrict__ bii, const float* __restrict__ bif,
                           const float* __restrict__ big, const float* __restrict__ bio,
                           const float* __restrict__ bhi, const float* __restrict__ bhf,
                           const float* __restrict__ bhg, const float* __restrict__ bho) {
    int j = blockIdx.x * blockDim.x + threadIdx.x;
    if (j >= G4) return;
    int gate = j >> 10, n = j & 1023;
    float a, b;
    switch (gate) {
        case 0:  a = bii[n]; b = bhi[n]; break;
        case 1:  a = bif[n]; b = bhf[n]; break;
        case 2:  a = big[n]; b = bhg[n]; break;
        default: a = bio[n]; b = bho[n]; break;
    }
    g_bias[j] = a + b;
}

__global__ void init_state(const float* __restrict__ h0, const float* __restrict__ c0) {
    int i = blockIdx.x * blockDim.x + threadIdx.x;
    if (i < B_ * H_) { g_h[0][i] = h0[i]; g_c[i] = c0[i]; }
}

// ---------------- phase 1: x_proj GEMM ----------------
// C[r][n] = sum_k inputs_row(r)[k] * g_Wi[n][k] + bias[n]
// r = t*B + b ;  inputs row ptr = inputs + (b*S + t)*IN
// Tile 128x128, BK=32, 256 threads = 8 warps (2 x 4), warp tile 64x32 (4x4 frags)
__global__ __launch_bounds__(256) void gemm_xproj(const float* __restrict__ inputs) {
    __shared__ unsigned As[128][36];
    __shared__ unsigned Bs[128][36];

    const int tid  = threadIdx.x;
    const int lane = tid & 31, wid = tid >> 5;
    const int wm0 = (wid & 1) * 64;
    const int wn0 = (wid >> 1) * 32;
    const int g = lane >> 2, tq = lane & 3;
    const int bm = blockIdx.y, bn = blockIdx.x;

    float acc[4][4][4];
#pragma unroll
    for (int i = 0; i < 4; i++)
#pragma unroll
        for (int j = 0; j < 4; j++)
#pragma unroll
            for (int k = 0; k < 4; k++) acc[i][j][k] = 0.f;

    for (int kt = 0; kt < IN_ / 32; kt++) {
        const int k0 = kt * 32;
        // stage A: 128 rows x 32 k
#pragma unroll
        for (int i = 0; i < 4; i++) {
            int id = i * 256 + tid;
            int mr = id >> 3, kq = id & 7;
            int r = bm * 128 + mr;
            int b = r & 63, tt = r >> 6;
            float4 v = *reinterpret_cast<const float4*>(
                inputs + ((size_t)b * S_ + tt) * IN_ + k0 + kq * 4);
            As[mr][kq * 4 + 0] = f2tf(v.x);
            As[mr][kq * 4 + 1] = f2tf(v.y);
            As[mr][kq * 4 + 2] = f2tf(v.z);
            As[mr][kq * 4 + 3] = f2tf(v.w);
        }
        // stage B (weights): 128 n-rows x 32 k
#pragma unroll
        for (int i = 0; i < 4; i++) {
            int id = i * 256 + tid;
            int nr = id >> 3, kq = id & 7;
            float4 v = *reinterpret_cast<const float4*>(
                g_Wi + (size_t)(bn * 128 + nr) * IN_ + k0 + kq * 4);
            Bs[nr][kq * 4 + 0] = f2tf(v.x);
            Bs[nr][kq * 4 + 1] = f2tf(v.y);
            Bs[nr][kq * 4 + 2] = f2tf(v.z);
            Bs[nr][kq * 4 + 3] = f2tf(v.w);
        }
        __syncthreads();

#pragma unroll
        for (int ks = 0; ks < 4; ks++) {
            unsigned a[4][4], bf[4][2];
#pragma unroll
            for (int mf = 0; mf < 4; mf++) {
                int row = wm0 + mf * 16 + g;
                a[mf][0] = As[row][ks * 8 + tq];
                a[mf][1] = As[row + 8][ks * 8 + tq];
                a[mf][2] = As[row][ks * 8 + tq + 4];
                a[mf][3] = As[row + 8][ks * 8 + tq + 4];
            }
#pragma unroll
            for (int nf = 0; nf < 4; nf++) {
                int row = wn0 + nf * 8 + g;
                bf[nf][0] = Bs[row][ks * 8 + tq];
                bf[nf][1] = Bs[row][ks * 8 + tq + 4];
            }
#pragma unroll
            for (int mf = 0; mf < 4; mf++)
#pragma unroll
                for (int nf = 0; nf < 4; nf++) mma8(acc[mf][nf], a[mf], bf[nf]);
        }
        __syncthreads();
    }

    // epilogue: add bias, store to g_xp
#pragma unroll
    for (int mf = 0; mf < 4; mf++) {
        int r0 = bm * 128 + wm0 + mf * 16 + g;
#pragma unroll
        for (int nf = 0; nf < 4; nf++) {
            int col = bn * 128 + wn0 + nf * 8 + 2 * tq;
            float b0 = g_bias[col], b1 = g_bias[col + 1];
            float* d0 = g_xp + (size_t)r0 * G4 + col;
            d0[0] = acc[mf][nf][0] + b0;
            d0[1] = acc[mf][nf][1] + b1;
            float* d1 = g_xp + (size_t)(r0 + 8) * G4 + col;
            d1[0] = acc[mf][nf][2] + b0;
            d1[1] = acc[mf][nf][3] + b1;
        }
    }
}

// ---------------- phase 2: one recurrent step ----------------
// Grid: 128 CTAs; CTA nt handles hidden units n0..n0+7 (x4 gates = 32 gate cols),
// all 64 batches, full K=1024. 128 threads = 4 warps; warp w owns cols [w*8, w*8+8).
__global__ __launch_bounds__(128) void lstm_step(float* __restrict__ out, int t) {
    __shared__ unsigned Hs[64][36];
    __shared__ unsigned Ws[32][36];
    __shared__ float Gs[64][33];

    const int tid = threadIdx.x, lane = tid & 31, w = tid >> 5;
    const int g = lane >> 2, tq = lane & 3;
    const int n0 = blockIdx.x * 8;
    const float* __restrict__ hsrc = g_h[t & 1];

    float acc[4][4];
#pragma unroll
    for (int i = 0; i < 4; i++)
#pragma unroll
        for (int j = 0; j < 4; j++) acc[i][j] = 0.f;

    for (int kt = 0; kt < H_ / 32; kt++) {
        const int k0 = kt * 32;
        // stage h tile: 64 x 32
#pragma unroll
        for (int i = 0; i < 4; i++) {
            int id = i * 128 + tid;
            int b = id >> 3, kq = id & 7;
            float4 v = *reinterpret_cast<const float4*>(hsrc + b * H_ + k0 + kq * 4);
            Hs[b][kq * 4 + 0] = f2tf(v.x);
            Hs[b][kq * 4 + 1] = f2tf(v.y);
            Hs[b][kq * 4 + 2] = f2tf(v.z);
            Hs[b][kq * 4 + 3] = f2tf(v.w);
        }
        // stage Wh tile: 32 gate-cols x 32 k
#pragma unroll
        for (int i = 0; i < 2; i++) {
            int id = i * 128 + tid;
            int c = id >> 3, kq = id & 7;
            int wr = (c >> 3) * H_ + n0 + (c & 7);   // global Wh row for gate-col c
            float4 v = *reinterpret_cast<const float4*>(
                g_Wh + (size_t)wr * H_ + k0 + kq * 4);
            Ws[c][kq * 4 + 0] = f2tf(v.x);
            Ws[c][kq * 4 + 1] = f2tf(v.y);
            Ws[c][kq * 4 + 2] = f2tf(v.z);
            Ws[c][kq * 4 + 3] = f2tf(v.w);
        }
        __syncthreads();

#pragma unroll
        for (int ks = 0; ks < 4; ks++) {
            unsigned a[4][4], bf[2];
#pragma unroll
            for (int mf = 0; mf < 4; mf++) {
                int row = mf * 16 + g;
                a[mf][0] = Hs[row][ks * 8 + tq];
                a[mf][1] = Hs[row + 8][ks * 8 + tq];
                a[mf][2] = Hs[row][ks * 8 + tq + 4];
                a[mf][3] = Hs[row + 8][ks * 8 + tq + 4];
            }
            int brow = w * 8 + g;
            bf[0] = Ws[brow][ks * 8 + tq];
            bf[1] = Ws[brow][ks * 8 + tq + 4];
#pragma unroll
            for (int mf = 0; mf < 4; mf++) mma8(acc[mf], a[mf], bf);
        }
        __syncthreads();
    }

    // gather h@Wh^T into smem (grouped so one thread sees all 4 gates of (b, n))
#pragma unroll
    for (int mf = 0; mf < 4; mf++) {
        Gs[mf * 16 + g][w * 8 + 2 * tq]         = acc[mf][0];
        Gs[mf * 16 + g][w * 8 + 2 * tq + 1]     = acc[mf][1];
        Gs[mf * 16 + g + 8][w * 8 + 2 * tq]     = acc[mf][2];
        Gs[mf * 16 + g + 8][w * 8 + 2 * tq + 1] = acc[mf][3];
    }
    __syncthreads();

    float* __restrict__ hdst = g_h[(t + 1) & 1];
    const float* __restrict__ xp = g_xp + (size_t)t * B_ * G4;
#pragma unroll
    for (int i = 0; i < 4; i++) {
        int e = i * 128 + tid;
        int b = e >> 3, nn = e & 7;
        int n = n0 + nn;
        const float* xpb = xp + (size_t)b * G4;
        float xi = Gs[b][nn]      + xpb[n];
        float xf = Gs[b][8 + nn]  + xpb[1024 + n];
        float xg = Gs[b][16 + nn] + xpb[2048 + n];
        float xo = Gs[b][24 + nn] + xpb[3072 + n];
        float iv = 1.f / (1.f + expf(-xi));
        float fv = 1.f / (1.f + expf(-xf));
        float gv = tanhf(xg);
        float ov = 1.f / (1.f + expf(-xo));
        float cn = fv * g_c[b * H_ + n] + iv * gv;
        g_c[b * H_ + n] = cn;
        float hn = ov * tanhf(cn);
        hdst[b * H_ + n] = hn;
        out[((size_t)b * S_ + t) * H_ + n] = hn;
    }
}

// ---------------- tail: final (h, c) ----------------
__global__ void tail_hc(float* __restrict__ out) {
    int i = blockIdx.x * blockDim.x + threadIdx.x;
    if (i < B_ * H_) {
        out[(size_t)B_ * S_ * H_ + i] = g_h[S_ & 1][i];           // h_f (buffer 0 after t=511)
        out[(size_t)B_ * S_ * H_ + B_ * H_ + i] = g_c[i];          // c_f
    }
}

// ---------------- launch ----------------
extern "C" void kernel_launch(void* const* d_in, const int* in_sizes, int n_in,
                              void* d_out, int out_size) {
    const float* inputs = (const float*)d_in[0];
    const float* h0     = (const float*)d_in[1];
    const float* c0     = (const float*)d_in[2];
    // weights 3..6 = w_ii,w_if,w_ig,w_io ; 7..10 = b_i* ; 11..14 = w_h* ; 15..18 = b_h*
    float* out = (float*)d_out;

    for (int gt = 0; gt < 4; gt++)
        pack_wi<<<(H_ * IN_ / 4 + 255) / 256, 256>>>((const float*)d_in[3 + gt], gt);
    for (int gt = 0; gt < 4; gt++)
        pack_wh<<<(H_ * H_ / 4 + 255) / 256, 256>>>((const float*)d_in[11 + gt], gt);
    build_bias<<<(G4 + 255) / 256, 256>>>(
        (const float*)d_in[7], (const float*)d_in[8],
        (const float*)d_in[9], (const float*)d_in[10],
        (const float*)d_in[15], (const float*)d_in[16],
        (const float*)d_in[17], (const float*)d_in[18]);
    init_state<<<(B_ * H_ + 255) / 256, 256>>>(h0, c0);

    gemm_xproj<<<dim3(G4 / 128, (S_ * B_) / 128), 256>>>(inputs);

    for (int t = 0; t < S_; t++) lstm_step<<<128, 128>>>(out, t);

    if (out_size >= B_ * S_ * H_ + 2 * B_ * H_)
        tail_hc<<<(B_ * H_ + 255) / 256, 256>>>(out);
}

// round 2
// speedup vs baseline: 2.1653x; 2.1653x over previous
#include <cuda_runtime.h>
#include <cstdint>
#include <math.h>

// Problem dims
#define B_   64
#define S_   512
#define H_   1024
#define IN_  1024
#define G4   4096   // 4*H
#define NCTA 128    // persistent grid

// ---------------- device scratch (no runtime allocation allowed) ----------------
__device__ float g_Wi[(size_t)G4 * IN_];          // 16 MB, tf32 bits, packed [i;f;g;o] x IN
__device__ float g_Wh[(size_t)G4 * H_];           // 16 MB, tf32 bits
__device__ float g_bias[G4];
__device__ float g_xin[(size_t)S_ * B_ * IN_];    // 128 MB, inputs transposed to [t*B+b][k], tf32 bits
__device__ float g_xp[(size_t)S_ * B_ * G4];      // 512 MB  x_proj [t][b][4H]
__device__ float g_htf[2][B_ * H_];               // h double buffer, tf32 bits
__device__ unsigned g_bar_cnt;
__device__ volatile unsigned g_bar_gen;

// ---------------- helpers ----------------
__device__ __forceinline__ unsigned f2tf(float x) {
    unsigned u;
    asm("cvt.rna.tf32.f32 %0, %1;" : "=r"(u) : "f"(x));
    return u;
}
__device__ __forceinline__ float f2tf_f(float x) { return __uint_as_float(f2tf(x)); }

__device__ __forceinline__ void mma8(float* d, const unsigned* a, const unsigned* b) {
    asm volatile(
        "mma.sync.aligned.m16n8k8.row.col.f32.tf32.tf32.f32 "
        "{%0,%1,%2,%3}, {%4,%5,%6,%7}, {%8,%9}, {%0,%1,%2,%3};\n"
        : "+f"(d[0]), "+f"(d[1]), "+f"(d[2]), "+f"(d[3])
        : "r"(a[0]), "r"(a[1]), "r"(a[2]), "r"(a[3]), "r"(b[0]), "r"(b[1]));
}

__device__ __forceinline__ void cpasync16(void* smem_dst, const void* gsrc) {
    unsigned saddr = (unsigned)__cvta_generic_to_shared(smem_dst);
    asm volatile("cp.async.cg.shared.global [%0], [%1], 16;\n" :: "r"(saddr), "l"(gsrc));
}
#define CP_COMMIT()  asm volatile("cp.async.commit_group;\n")
#define CP_WAIT(n)   asm volatile("cp.async.wait_group %0;\n" :: "n"(n))

// ---------------- setup kernels ----------------
__global__ void pack_wi(const float* __restrict__ src, int gate) {
    int i = blockIdx.x * blockDim.x + threadIdx.x;
    const int n4 = H_ * IN_ / 4;
    if (i < n4) {
        float4 v = reinterpret_cast<const float4*>(src)[i];
        float4 o;
        o.x = f2tf_f(v.x); o.y = f2tf_f(v.y); o.z = f2tf_f(v.z); o.w = f2tf_f(v.w);
        reinterpret_cast<float4*>(g_Wi)[(size_t)gate * n4 + i] = o;
    }
}
__global__ void pack_wh(const float* __restrict__ src, int gate) {
    int i = blockIdx.x * blockDim.x + threadIdx.x;
    const int n4 = H_ * H_ / 4;
    if (i < n4) {
        float4 v = reinterpret_cast<const float4*>(src)[i];
        float4 o;
        o.x = f2tf_f(v.x); o.y = f2tf_f(v.y); o.z = f2tf_f(v.z); o.w = f2tf_f(v.w);
        reinterpret_cast<float4*>(g_Wh)[(size_t)gate * n4 + i] = o;
    }
}
__global__ void conv_inputs(const float* __restrict__ src) {
    size_t id = (size_t)blockIdx.x * blockDim.x + threadIdx.x;
    const size_t n4 = (size_t)B_ * S_ * IN_ / 4;
    if (id < n4) {
        size_t r = id >> 8;               // row t*64+b
        int q = (int)(id & 255);
        int t = (int)(r >> 6), b = (int)(r & 63);
        float4 v = *reinterpret_cast<const float4*>(src + ((size_t)b * S_ + t) * IN_ + q * 4);
        float4 o;
        o.x = f2tf_f(v.x); o.y = f2tf_f(v.y); o.z = f2tf_f(v.z); o.w = f2tf_f(v.w);
        *reinterpret_cast<float4*>(g_xin + r * IN_ + q * 4) = o;
    }
}
__global__ void build_bias(const float* __restrict__ bii, const float* __restrict__ bif,
                           const float* __restrict__ big, const float* __restrict__ bio,
                           const float* __restrict__ bhi, const float* __restrict__ bhf,
                           const float* __restrict__ bhg, const float* __restrict__ bho) {
    int j = blockIdx.x * blockDim.x + threadIdx.x;
    if (j >= G4) return;
    int gate = j >> 10, n = j & 1023;
    float a, b;
    switch (gate) {
        case 0:  a = bii[n]; b = bhi[n]; break;
        case 1:  a = bif[n]; b = bhf[n]; break;
        case 2:  a = big[n]; b = bhg[n]; break;
        default: a = bio[n]; b = bho[n]; break;
    }
    g_bias[j] = a + b;
}
__global__ void init_state(const float* __restrict__ h0) {
    int i = blockIdx.x * blockDim.x + threadIdx.x;
    if (i < B_ * H_) g_htf[0][i] = f2tf_f(h0[i]);
    if (i == 0) { g_bar_cnt = 0; g_bar_gen = 0; }
}

// ---------------- phase 1: x_proj GEMM (cp.async double-buffered) ----------------
// C[r][n] = sum_k g_xin[r][k] * g_Wi[n][k] + bias[n],  r = t*B+b
// Tile 128x128, BK=32, 256 thr = 8 warps (2 m x 4 n), warp tile 64x32.
__global__ __launch_bounds__(256) void gemm_xproj() {
    extern __shared__ unsigned sm[];
    unsigned* As = sm;                    // [2][128][36]
    unsigned* Bs = sm + 2 * 128 * 36;     // [2][128][36]

    const int tid  = threadIdx.x;
    const int lane = tid & 31, wid = tid >> 5;
    const int wm0 = (wid & 1) * 64;
    const int wn0 = (wid >> 1) * 32;
    const int g = lane >> 2, tq = lane & 3;
    const int bm = blockIdx.y, bn = blockIdx.x;

    float acc[4][4][4];
#pragma unroll
    for (int i = 0; i < 4; i++)
#pragma unroll
        for (int j = 0; j < 4; j++)
#pragma unroll
            for (int k = 0; k < 4; k++) acc[i][j][k] = 0.f;

    const int mr = tid >> 3, kq = tid & 7;   // each thread: 4 rows apart (stride 32)

    auto stage = [&](int buf, int kt) {
        const int k0 = kt * 32;
#pragma unroll
        for (int i = 0; i < 4; i++) {
            int row = mr + i * 32;
            cpasync16(&As[(buf * 128 + row) * 36 + kq * 4],
                      g_xin + (size_t)(bm * 128 + row) * IN_ + k0 + kq * 4);
        }
#pragma unroll
        for (int i = 0; i < 4; i++) {
            int row = mr + i * 32;
            cpasync16(&Bs[(buf * 128 + row) * 36 + kq * 4],
                      g_Wi + (size_t)(bn * 128 + row) * IN_ + k0 + kq * 4);
        }
        CP_COMMIT();
    };

    stage(0, 0);
    int buf = 0;
#pragma unroll 1
    for (int kt = 0; kt < IN_ / 32; kt++) {
        if (kt + 1 < IN_ / 32) { stage(buf ^ 1, kt + 1); CP_WAIT(1); }
        else                   { CP_WAIT(0); }
        __syncthreads();

        const unsigned* Ab = As + buf * 128 * 36;
        const unsigned* Bb = Bs + buf * 128 * 36;
#pragma unroll
        for (int ks = 0; ks < 4; ks++) {
            unsigned a[4][4], bf[4][2];
#pragma unroll
            for (int mf = 0; mf < 4; mf++) {
                int row = wm0 + mf * 16 + g;
                a[mf][0] = Ab[row * 36 + ks * 8 + tq];
                a[mf][1] = Ab[(row + 8) * 36 + ks * 8 + tq];
                a[mf][2] = Ab[row * 36 + ks * 8 + tq + 4];
                a[mf][3] = Ab[(row + 8) * 36 + ks * 8 + tq + 4];
            }
#pragma unroll
            for (int nf = 0; nf < 4; nf++) {
                int row = wn0 + nf * 8 + g;
                bf[nf][0] = Bb[row * 36 + ks * 8 + tq];
                bf[nf][1] = Bb[row * 36 + ks * 8 + tq + 4];
            }
#pragma unroll
            for (int mf = 0; mf < 4; mf++)
#pragma unroll
                for (int nf = 0; nf < 4; nf++) mma8(acc[mf][nf], a[mf], bf[nf]);
        }
        __syncthreads();
        buf ^= 1;
    }

#pragma unroll
    for (int mf = 0; mf < 4; mf++) {
        int r0 = bm * 128 + wm0 + mf * 16 + g;
#pragma unroll
        for (int nf = 0; nf < 4; nf++) {
            int col = bn * 128 + wn0 + nf * 8 + 2 * tq;
            float b0 = g_bias[col], b1 = g_bias[col + 1];
            float* d0 = g_xp + (size_t)r0 * G4 + col;
            d0[0] = acc[mf][nf][0] + b0;
            d0[1] = acc[mf][nf][1] + b1;
            float* d1 = g_xp + (size_t)(r0 + 8) * G4 + col;
            d1[0] = acc[mf][nf][2] + b0;
            d1[1] = acc[mf][nf][3] + b1;
        }
    }
}

// ---------------- phase 2: persistent recurrence ----------------
// 128 CTAs x 128 threads. CTA owns hidden units n0..n0+7 (32 gate cols), Wh slice
// resident in smem for all 512 steps. Warp w owns batch rows [w*16, w*16+16).
__device__ __forceinline__ void grid_sync_() {
    __syncthreads();
    if (threadIdx.x == 0) {
        unsigned gen = g_bar_gen;
        __threadfence();
        if (atomicAdd(&g_bar_cnt, 1u) == NCTA - 1) {
            g_bar_cnt = 0;
            __threadfence();
            g_bar_gen = gen + 1;
        } else {
            while (g_bar_gen == gen) {}
            __threadfence();
        }
    }
    __syncthreads();
}

__global__ __launch_bounds__(128) void lstm_persistent(float* __restrict__ out,
                                                       const float* __restrict__ c0) {
    extern __shared__ unsigned smp[];
    unsigned* ws = smp;                         // [32][1028] tf32 Wh slice
    unsigned* hs = ws + 32 * 1028;              // [64][36]   tf32 h tile
    float*    gs = (float*)(hs + 64 * 36);      // [64][33]   h@Wh^T gather

    const int tid = threadIdx.x, lane = tid & 31, w = tid >> 5;
    const int g = lane >> 2, tq = lane & 3;
    const int n0 = blockIdx.x * 8;

    // load Wh slice into smem once (pre-converted tf32 bits)
    for (int id = tid; id < 8192; id += 128) {
        int c = id >> 8;                 // gate col 0..31
        int q = id & 255;                // float4 index
        int wr = (c >> 3) * H_ + n0 + (c & 7);
        float4 v = *reinterpret_cast<const float4*>(g_Wh + (size_t)wr * H_ + q * 4);
        unsigned* d = ws + c * 1028 + q * 4;
        d[0] = __float_as_uint(v.x); d[1] = __float_as_uint(v.y);
        d[2] = __float_as_uint(v.z); d[3] = __float_as_uint(v.w);
    }

    // per-thread cell state in registers for the whole sequence
    float c_reg[4];
#pragma unroll
    for (int i = 0; i < 4; i++) {
        int e = i * 128 + tid;
        int b = e >> 3, nn = e & 7;
        c_reg[i] = c0[b * H_ + n0 + nn];
    }

    const int sb = tid >> 3, skq = tid & 7;    // h-tile staging coords (8 rows per 64 thr grp)

#pragma unroll 1
    for (int t = 0; t < S_; t++) {
        grid_sync_();
        const float* __restrict__ hsrc = g_htf[t & 1];

        float4 R[4];
#pragma unroll
        for (int j = 0; j < 4; j++)
            R[j] = *reinterpret_cast<const float4*>(hsrc + (sb + j * 16) * H_ + skq * 4);

        float acc[4][4];
#pragma unroll
        for (int i = 0; i < 4; i++)
#pragma unroll
            for (int j = 0; j < 4; j++) acc[i][j] = 0.f;

#pragma unroll 1
        for (int kt = 0; kt < H_ / 32; kt++) {
#pragma unroll
            for (int j = 0; j < 4; j++) {
                unsigned* d = hs + (sb + j * 16) * 36 + skq * 4;
                d[0] = __float_as_uint(R[j].x); d[1] = __float_as_uint(R[j].y);
                d[2] = __float_as_uint(R[j].z); d[3] = __float_as_uint(R[j].w);
            }
            __syncthreads();
            if (kt + 1 < H_ / 32) {
                int k0n = (kt + 1) * 32;
#pragma unroll
                for (int j = 0; j < 4; j++)
                    R[j] = *reinterpret_cast<const float4*>(
                        hsrc + (sb + j * 16) * H_ + k0n + skq * 4);
            }
            const int k0 = kt * 32;
#pragma unroll
            for (int ks = 0; ks < 4; ks++) {
                unsigned a[4];
                int arow = w * 16 + g;
                a[0] = hs[arow * 36 + ks * 8 + tq];
                a[1] = hs[(arow + 8) * 36 + ks * 8 + tq];
                a[2] = hs[arow * 36 + ks * 8 + tq + 4];
                a[3] = hs[(arow + 8) * 36 + ks * 8 + tq + 4];
#pragma unroll
                for (int nf = 0; nf < 4; nf++) {
                    unsigned bfr[2];
                    int brow = nf * 8 + g;
                    bfr[0] = ws[brow * 1028 + k0 + ks * 8 + tq];
                    bfr[1] = ws[brow * 1028 + k0 + ks * 8 + tq + 4];
                    mma8(acc[nf], a, bfr);
                }
            }
            __syncthreads();
        }

        // gather gates to smem: rows = batches owned by this warp
#pragma unroll
        for (int nf = 0; nf < 4; nf++) {
            int r = w * 16 + g;
            gs[r * 33 + nf * 8 + 2 * tq]           = acc[nf][0];
            gs[r * 33 + nf * 8 + 2 * tq + 1]       = acc[nf][1];
            gs[(r + 8) * 33 + nf * 8 + 2 * tq]     = acc[nf][2];
            gs[(r + 8) * 33 + nf * 8 + 2 * tq + 1] = acc[nf][3];
        }
        __syncthreads();

        float* __restrict__ hdst = g_htf[(t + 1) & 1];
        const float* __restrict__ xpb_base = g_xp + (size_t)t * B_ * G4;
#pragma unroll
        for (int i = 0; i < 4; i++) {
            int e = i * 128 + tid;
            int b = e >> 3, nn = e & 7;
            int n = n0 + nn;
            const float* xpb = xpb_base + (size_t)b * G4;
            float xi = gs[b * 33 + nn]       + xpb[n];
            float xf = gs[b * 33 + 8 + nn]   + xpb[1024 + n];
            float xg = gs[b * 33 + 16 + nn]  + xpb[2048 + n];
            float xo = gs[b * 33 + 24 + nn]  + xpb[3072 + n];
            float iv = 1.f / (1.f + expf(-xi));
            float fv = 1.f / (1.f + expf(-xf));
            float gv = tanhf(xg);
            float ov = 1.f / (1.f + expf(-xo));
            float cn = fv * c_reg[i] + iv * gv;
            c_reg[i] = cn;
            float hn = ov * tanhf(cn);
            hdst[b * H_ + n] = f2tf_f(hn);
            out[((size_t)b * S_ + t) * H_ + n] = hn;
            if (t == S_ - 1) {
                out[(size_t)B_ * S_ * H_ + b * H_ + n] = hn;                 // h_f
                out[(size_t)B_ * S_ * H_ + B_ * H_ + b * H_ + n] = cn;       // c_f
            }
        }
        // next iteration's grid_sync starts with __syncthreads(), protecting gs/hs reuse
    }
}

// ---------------- launch ----------------
extern "C" void kernel_launch(void* const* d_in, const int* in_sizes, int n_in,
                              void* d_out, int out_size) {
    const float* inputs = (const float*)d_in[0];
    const float* h0     = (const float*)d_in[1];
    const float* c0     = (const float*)d_in[2];
    float* out = (float*)d_out;

    const int GEMM_SMEM = 2 * 128 * 36 * 4 * 2;                 // 73,728 B
    const int PERS_SMEM = (32 * 1028 + 64 * 36) * 4 + 64 * 33 * 4;  // 149,248 B
    cudaFuncSetAttribute(gemm_xproj, cudaFuncAttributeMaxDynamicSharedMemorySize, GEMM_SMEM);
    cudaFuncSetAttribute(lstm_persistent, cudaFuncAttributeMaxDynamicSharedMemorySize, PERS_SMEM);

    for (int gt = 0; gt < 4; gt++)
        pack_wi<<<(H_ * IN_ / 4 + 255) / 256, 256>>>((const float*)d_in[3 + gt], gt);
    for (int gt = 0; gt < 4; gt++)
        pack_wh<<<(H_ * H_ / 4 + 255) / 256, 256>>>((const float*)d_in[11 + gt], gt);
    conv_inputs<<<(int)(((size_t)B_ * S_ * IN_ / 4 + 255) / 256), 256>>>(inputs);
    build_bias<<<(G4 + 255) / 256, 256>>>(
        (const float*)d_in[7], (const float*)d_in[8],
        (const float*)d_in[9], (const float*)d_in[10],
        (const float*)d_in[15], (const float*)d_in[16],
        (const float*)d_in[17], (const float*)d_in[18]);
    init_state<<<(B_ * H_ + 255) / 256, 256>>>(h0);

    gemm_xproj<<<dim3(G4 / 128, (S_ * B_) / 128), 256, GEMM_SMEM>>>();

    lstm_persistent<<<NCTA, 128, PERS_SMEM>>>(out, c0);
}

// round 4
// speedup vs baseline: 2.1667x; 1.0007x over previous
#include <cuda_runtime.h>
#include <cstdint>
#include <math.h>

// Problem dims
#define B_   64
#define S_   512
#define H_   1024
#define IN_  1024
#define G4   4096   // 4*H
#define NCTA 128    // persistent grid

// ---------------- device scratch (no runtime allocation allowed) ----------------
__device__ float g_Wi[(size_t)G4 * IN_];          // 16 MB, tf32 bits, packed [i;f;g;o] x IN
__device__ float g_Wh[(size_t)G4 * H_];           // 16 MB, tf32 bits
__device__ float g_bias[G4];
__device__ float g_xin[(size_t)S_ * B_ * IN_];    // 128 MB, inputs transposed to [t*B+b][k], tf32 bits
__device__ float g_xp[(size_t)S_ * B_ * G4];      // 512 MB  x_proj [t][b][4H]
__device__ float g_htf[2][B_ * H_];               // h double buffer, tf32 bits
__device__ unsigned g_bar_cnt;
__device__ volatile unsigned g_bar_gen;

// ---------------- helpers ----------------
__device__ __forceinline__ unsigned f2tf(float x) {
    unsigned u;
    asm("cvt.rna.tf32.f32 %0, %1;" : "=r"(u) : "f"(x));
    return u;
}
__device__ __forceinline__ float f2tf_f(float x) { return __uint_as_float(f2tf(x)); }

__device__ __forceinline__ void mma8(float* d, const unsigned* a, const unsigned* b) {
    asm volatile(
        "mma.sync.aligned.m16n8k8.row.col.f32.tf32.tf32.f32 "
        "{%0,%1,%2,%3}, {%4,%5,%6,%7}, {%8,%9}, {%0,%1,%2,%3};\n"
        : "+f"(d[0]), "+f"(d[1]), "+f"(d[2]), "+f"(d[3])
        : "r"(a[0]), "r"(a[1]), "r"(a[2]), "r"(a[3]), "r"(b[0]), "r"(b[1]));
}

__device__ __forceinline__ void cpasync16(void* smem_dst, const void* gsrc) {
    unsigned saddr = (unsigned)__cvta_generic_to_shared(smem_dst);
    asm volatile("cp.async.cg.shared.global [%0], [%1], 16;\n" :: "r"(saddr), "l"(gsrc));
}
#define CP_COMMIT()  asm volatile("cp.async.commit_group;\n")
#define CP_WAIT(n)   asm volatile("cp.async.wait_group %0;\n" :: "n"(n))

// ---------------- setup kernels ----------------
__global__ void pack_wi(const float* __restrict__ src, int gate) {
    int i = blockIdx.x * blockDim.x + threadIdx.x;
    const int n4 = H_ * IN_ / 4;
    if (i < n4) {
        float4 v = reinterpret_cast<const float4*>(src)[i];
        float4 o;
        o.x = f2tf_f(v.x); o.y = f2tf_f(v.y); o.z = f2tf_f(v.z); o.w = f2tf_f(v.w);
        reinterpret_cast<float4*>(g_Wi)[(size_t)gate * n4 + i] = o;
    }
}
__global__ void pack_wh(const float* __restrict__ src, int gate) {
    int i = blockIdx.x * blockDim.x + threadIdx.x;
    const int n4 = H_ * H_ / 4;
    if (i < n4) {
        float4 v = reinterpret_cast<const float4*>(src)[i];
        float4 o;
        o.x = f2tf_f(v.x); o.y = f2tf_f(v.y); o.z = f2tf_f(v.z); o.w = f2tf_f(v.w);
        reinterpret_cast<float4*>(g_Wh)[(size_t)gate * n4 + i] = o;
    }
}
__global__ void conv_inputs(const float* __restrict__ src) {
    size_t id = (size_t)blockIdx.x * blockDim.x + threadIdx.x;
    const size_t n4 = (size_t)B_ * S_ * IN_ / 4;
    if (id < n4) {
        size_t r = id >> 8;               // row t*64+b
        int q = (int)(id & 255);
        int t = (int)(r >> 6), b = (int)(r & 63);
        float4 v = *reinterpret_cast<const float4*>(src + ((size_t)b * S_ + t) * IN_ + q * 4);
        float4 o;
        o.x = f2tf_f(v.x); o.y = f2tf_f(v.y); o.z = f2tf_f(v.z); o.w = f2tf_f(v.w);
        *reinterpret_cast<float4*>(g_xin + r * IN_ + q * 4) = o;
    }
}
__global__ void build_bias(const float* __restrict__ bii, const float* __restrict__ bif,
                           const float* __restrict__ big, const float* __restrict__ bio,
                           const float* __restrict__ bhi, const float* __restrict__ bhf,
                           const float* __restrict__ bhg, const float* __restrict__ bho) {
    int j = blockIdx.x * blockDim.x + threadIdx.x;
    if (j >= G4) return;
    int gate = j >> 10, n = j & 1023;
    float a, b;
    switch (gate) {
        case 0:  a = bii[n]; b = bhi[n]; break;
        case 1:  a = bif[n]; b = bhf[n]; break;
        case 2:  a = big[n]; b = bhg[n]; break;
        default: a = bio[n]; b = bho[n]; break;
    }
    g_bias[j] = a + b;
}
__global__ void init_state(const float* __restrict__ h0) {
    int i = blockIdx.x * blockDim.x + threadIdx.x;
    if (i < B_ * H_) g_htf[0][i] = f2tf_f(h0[i]);
    if (i == 0) { g_bar_cnt = 0; g_bar_gen = 0; }
}

// ---------------- phase 1: x_proj GEMM (cp.async double-buffered) ----------------
// C[r][n] = sum_k g_xin[r][k] * g_Wi[n][k] + bias[n],  r = t*B+b
// Tile 128x128, BK=32, 256 thr = 8 warps (2 m x 4 n), warp tile 64x32.
__global__ __launch_bounds__(256) void gemm_xproj() {
    extern __shared__ unsigned sm[];
    unsigned* As = sm;                    // [2][128][36]
    unsigned* Bs = sm + 2 * 128 * 36;     // [2][128][36]

    const int tid  = threadIdx.x;
    const int lane = tid & 31, wid = tid >> 5;
    const int wm0 = (wid & 1) * 64;
    const int wn0 = (wid >> 1) * 32;
    const int g = lane >> 2, tq = lane & 3;
    const int bm = blockIdx.y, bn = blockIdx.x;

    float acc[4][4][4];
#pragma unroll
    for (int i = 0; i < 4; i++)
#pragma unroll
        for (int j = 0; j < 4; j++)
#pragma unroll
            for (int k = 0; k < 4; k++) acc[i][j][k] = 0.f;

    const int mr = tid >> 3, kq = tid & 7;   // each thread: 4 rows apart (stride 32)

    auto stage = [&](int buf, int kt) {
        const int k0 = kt * 32;
#pragma unroll
        for (int i = 0; i < 4; i++) {
            int row = mr + i * 32;
            cpasync16(&As[(buf * 128 + row) * 36 + kq * 4],
                      g_xin + (size_t)(bm * 128 + row) * IN_ + k0 + kq * 4);
        }
#pragma unroll
        for (int i = 0; i < 4; i++) {
            int row = mr + i * 32;
            cpasync16(&Bs[(buf * 128 + row) * 36 + kq * 4],
                      g_Wi + (size_t)(bn * 128 + row) * IN_ + k0 + kq * 4);
        }
        CP_COMMIT();
    };

    stage(0, 0);
    int buf = 0;
#pragma unroll 1
    for (int kt = 0; kt < IN_ / 32; kt++) {
        if (kt + 1 < IN_ / 32) { stage(buf ^ 1, kt + 1); CP_WAIT(1); }
        else                   { CP_WAIT(0); }
        __syncthreads();

        const unsigned* Ab = As + buf * 128 * 36;
        const unsigned* Bb = Bs + buf * 128 * 36;
#pragma unroll
        for (int ks = 0; ks < 4; ks++) {
            unsigned a[4][4], bf[4][2];
#pragma unroll
            for (int mf = 0; mf < 4; mf++) {
                int row = wm0 + mf * 16 + g;
                a[mf][0] = Ab[row * 36 + ks * 8 + tq];
                a[mf][1] = Ab[(row + 8) * 36 + ks * 8 + tq];
                a[mf][2] = Ab[row * 36 + ks * 8 + tq + 4];
                a[mf][3] = Ab[(row + 8) * 36 + ks * 8 + tq + 4];
            }
#pragma unroll
            for (int nf = 0; nf < 4; nf++) {
                int row = wn0 + nf * 8 + g;
                bf[nf][0] = Bb[row * 36 + ks * 8 + tq];
                bf[nf][1] = Bb[row * 36 + ks * 8 + tq + 4];
            }
#pragma unroll
            for (int mf = 0; mf < 4; mf++)
#pragma unroll
                for (int nf = 0; nf < 4; nf++) mma8(acc[mf][nf], a[mf], bf[nf]);
        }
        __syncthreads();
        buf ^= 1;
    }

#pragma unroll
    for (int mf = 0; mf < 4; mf++) {
        int r0 = bm * 128 + wm0 + mf * 16 + g;
#pragma unroll
        for (int nf = 0; nf < 4; nf++) {
            int col = bn * 128 + wn0 + nf * 8 + 2 * tq;
            float b0 = g_bias[col], b1 = g_bias[col + 1];
            float* d0 = g_xp + (size_t)r0 * G4 + col;
            d0[0] = acc[mf][nf][0] + b0;
            d0[1] = acc[mf][nf][1] + b1;
            float* d1 = g_xp + (size_t)(r0 + 8) * G4 + col;
            d1[0] = acc[mf][nf][2] + b0;
            d1[1] = acc[mf][nf][3] + b1;
        }
    }
}

// ---------------- phase 2: persistent recurrence ----------------
// 128 CTAs x 128 threads. CTA owns hidden units n0..n0+7 (32 gate cols), Wh slice
// resident in smem for all 512 steps. Warp w owns batch rows [w*16, w*16+16).
__device__ __forceinline__ void grid_sync_() {
    __syncthreads();
    if (threadIdx.x == 0) {
        unsigned gen = g_bar_gen;
        __threadfence();
        if (atomicAdd(&g_bar_cnt, 1u) == NCTA - 1) {
            g_bar_cnt = 0;
            __threadfence();
            g_bar_gen = gen + 1;
        } else {
            while (g_bar_gen == gen) {}
            __threadfence();
        }
    }
    __syncthreads();
}

__global__ __launch_bounds__(128) void lstm_persistent(float* __restrict__ out,
                                                       const float* __restrict__ c0) {
    extern __shared__ unsigned smp[];
    unsigned* ws = smp;                         // [32][1028] tf32 Wh slice
    unsigned* hs = ws + 32 * 1028;              // [64][36]   tf32 h tile
    float*    gs = (float*)(hs + 64 * 36);      // [64][33]   h@Wh^T gather

    const int tid = threadIdx.x, lane = tid & 31, w = tid >> 5;
    const int g = lane >> 2, tq = lane & 3;
    const int n0 = blockIdx.x * 8;

    // load Wh slice into smem once (pre-converted tf32 bits)
    for (int id = tid; id < 8192; id += 128) {
        int c = id >> 8;                 // gate col 0..31
        int q = id & 255;                // float4 index
        int wr = (c >> 3) * H_ + n0 + (c & 7);
        float4 v = *reinterpret_cast<const float4*>(g_Wh + (size_t)wr * H_ + q * 4);
        unsigned* d = ws + c * 1028 + q * 4;
        d[0] = __float_as_uint(v.x); d[1] = __float_as_uint(v.y);
        d[2] = __float_as_uint(v.z); d[3] = __float_as_uint(v.w);
    }

    // per-thread cell state in registers for the whole sequence
    float c_reg[4];
#pragma unroll
    for (int i = 0; i < 4; i++) {
        int e = i * 128 + tid;
        int b = e >> 3, nn = e & 7;
        c_reg[i] = c0[b * H_ + n0 + nn];
    }

    const int sb = tid >> 3, skq = tid & 7;    // h-tile staging coords (8 rows per 64 thr grp)

#pragma unroll 1
    for (int t = 0; t < S_; t++) {
        grid_sync_();
        const float* __restrict__ hsrc = g_htf[t & 1];

        float4 R[4];
#pragma unroll
        for (int j = 0; j < 4; j++)
            R[j] = *reinterpret_cast<const float4*>(hsrc + (sb + j * 16) * H_ + skq * 4);

        float acc[4][4];
#pragma unroll
        for (int i = 0; i < 4; i++)
#pragma unroll
            for (int j = 0; j < 4; j++) acc[i][j] = 0.f;

#pragma unroll 1
        for (int kt = 0; kt < H_ / 32; kt++) {
#pragma unroll
            for (int j = 0; j < 4; j++) {
                unsigned* d = hs + (sb + j * 16) * 36 + skq * 4;
                d[0] = __float_as_uint(R[j].x); d[1] = __float_as_uint(R[j].y);
                d[2] = __float_as_uint(R[j].z); d[3] = __float_as_uint(R[j].w);
            }
            __syncthreads();
            if (kt + 1 < H_ / 32) {
                int k0n = (kt + 1) * 32;
#pragma unroll
                for (int j = 0; j < 4; j++)
                    R[j] = *reinterpret_cast<const float4*>(
                        hsrc + (sb + j * 16) * H_ + k0n + skq * 4);
            }
            const int k0 = kt * 32;
#pragma unroll
            for (int ks = 0; ks < 4; ks++) {
                unsigned a[4];
                int arow = w * 16 + g;
                a[0] = hs[arow * 36 + ks * 8 + tq];
                a[1] = hs[(arow + 8) * 36 + ks * 8 + tq];
                a[2] = hs[arow * 36 + ks * 8 + tq + 4];
                a[3] = hs[(arow + 8) * 36 + ks * 8 + tq + 4];
#pragma unroll
                for (int nf = 0; nf < 4; nf++) {
                    unsigned bfr[2];
                    int brow = nf * 8 + g;
                    bfr[0] = ws[brow * 1028 + k0 + ks * 8 + tq];
                    bfr[1] = ws[brow * 1028 + k0 + ks * 8 + tq + 4];
                    mma8(acc[nf], a, bfr);
                }
            }
            __syncthreads();
        }

        // gather gates to smem: rows = batches owned by this warp
#pragma unroll
        for (int nf = 0; nf < 4; nf++) {
            int r = w * 16 + g;
            gs[r * 33 + nf * 8 + 2 * tq]           = acc[nf][0];
            gs[r * 33 + nf * 8 + 2 * tq + 1]       = acc[nf][1];
            gs[(r + 8) * 33 + nf * 8 + 2 * tq]     = acc[nf][2];
            gs[(r + 8) * 33 + nf * 8 + 2 * tq + 1] = acc[nf][3];
        }
        __syncthreads();

        float* __restrict__ hdst = g_htf[(t + 1) & 1];
        const float* __restrict__ xpb_base = g_xp + (size_t)t * B_ * G4;
#pragma unroll
        for (int i = 0; i < 4; i++) {
            int e = i * 128 + tid;
            int b = e >> 3, nn = e & 7;
            int n = n0 + nn;
            const float* xpb = xpb_base + (size_t)b * G4;
            float xi = gs[b * 33 + nn]       + xpb[n];
            float xf = gs[b * 33 + 8 + nn]   + xpb[1024 + n];
            float xg = gs[b * 33 + 16 + nn]  + xpb[2048 + n];
            float xo = gs[b * 33 + 24 + nn]  + xpb[3072 + n];
            float iv = 1.f / (1.f + expf(-xi));
            float fv = 1.f / (1.f + expf(-xf));
            float gv = tanhf(xg);
            float ov = 1.f / (1.f + expf(-xo));
            float cn = fv * c_reg[i] + iv * gv;
            c_reg[i] = cn;
            float hn = ov * tanhf(cn);
            hdst[b * H_ + n] = f2tf_f(hn);
            out[((size_t)b * S_ + t) * H_ + n] = hn;
            if (t == S_ - 1) {
                out[(size_t)B_ * S_ * H_ + b * H_ + n] = hn;                 // h_f
                out[(size_t)B_ * S_ * H_ + B_ * H_ + b * H_ + n] = cn;       // c_f
            }
        }
        // next iteration's grid_sync starts with __syncthreads(), protecting gs/hs reuse
    }
}

// ---------------- launch ----------------
extern "C" void kernel_launch(void* const* d_in, const int* in_sizes, int n_in,
                              void* d_out, int out_size) {
    const float* inputs = (const float*)d_in[0];
    const float* h0     = (const float*)d_in[1];
    const float* c0     = (const float*)d_in[2];
    float* out = (float*)d_out;

    const int GEMM_SMEM = 2 * 128 * 36 * 4 * 2;                 // 73,728 B
    const int PERS_SMEM = (32 * 1028 + 64 * 36) * 4 + 64 * 33 * 4;  // 149,248 B
    cudaFuncSetAttribute(gemm_xproj, cudaFuncAttributeMaxDynamicSharedMemorySize, GEMM_SMEM);
    cudaFuncSetAttribute(lstm_persistent, cudaFuncAttributeMaxDynamicSharedMemorySize, PERS_SMEM);

    for (int gt = 0; gt < 4; gt++)
        pack_wi<<<(H_ * IN_ / 4 + 255) / 256, 256>>>((const float*)d_in[3 + gt], gt);
    for (int gt = 0; gt < 4; gt++)
        pack_wh<<<(H_ * H_ / 4 + 255) / 256, 256>>>((const float*)d_in[11 + gt], gt);
    conv_inputs<<<(int)(((size_t)B_ * S_ * IN_ / 4 + 255) / 256), 256>>>(inputs);
    build_bias<<<(G4 + 255) / 256, 256>>>(
        (const float*)d_in[7], (const float*)d_in[8],
        (const float*)d_in[9], (const float*)d_in[10],
        (const float*)d_in[15], (const float*)d_in[16],
        (const float*)d_in[17], (const float*)d_in[18]);
    init_state<<<(B_ * H_ + 255) / 256, 256>>>(h0);

    gemm_xproj<<<dim3(G4 / 128, (S_ * B_) / 128), 256, GEMM_SMEM>>>();

    lstm_persistent<<<NCTA, 128, PERS_SMEM>>>(out, c0);
}